// round 16
// baseline (speedup 1.0000x reference)
#include <cuda_runtime.h>
#include <cuda_fp16.h>
#include <stdint.h>
#include <math.h>

#define SEQ   1024
#define HEADS 12
#define BATCH 16
#define DH    64
#define DIM   768
#define BHT   (BATCH*HEADS)   // 192
#define LOG2E 1.4426950408889634f
#define QSCALE (0.125f * LOG2E)   // folded into stored q

// fp16 operands + attention scratch
__device__ __half g_x16[(size_t)BATCH*SEQ*DIM];
__device__ __half g_w16[(size_t)3*DIM*DIM];
__device__ __half g_bh[(size_t)SEQ*SEQ];             // bias * log2e (fp16)
__device__ __half g_q[(size_t)BHT*SEQ*DH];           // pre-scaled by 0.125*log2e
__device__ __half g_k[(size_t)BHT*SEQ*DH];
__device__ __half g_v[(size_t)BHT*DH*SEQ];           // TRANSPOSED: [bh][chan][key]

__device__ __forceinline__ uint32_t s2u(const void* p) {
    return (uint32_t)__cvta_generic_to_shared(p);
}
__device__ __forceinline__ unsigned addh2(unsigned a, unsigned b) {
    unsigned d;
    asm("add.rn.f16x2 %0, %1, %2;" : "=r"(d) : "r"(a), "r"(b));
    return d;
}
__device__ __forceinline__ unsigned ex2h2(unsigned a) {
    unsigned d;
    asm("ex2.approx.f16x2 %0, %1;" : "=r"(d) : "r"(a));
    return d;
}
__device__ __forceinline__ void ldsm4(unsigned r[4], uint32_t a) {
    asm volatile("ldmatrix.sync.aligned.m8n8.x4.shared.b16 {%0,%1,%2,%3}, [%4];"
                 : "=r"(r[0]), "=r"(r[1]), "=r"(r[2]), "=r"(r[3]) : "r"(a));
}
// fp32-accumulator fp16 MMA (qkv GEMM + P*V)
__device__ __forceinline__ void mma_f16(float c[4], const unsigned a[4],
                                        unsigned b0, unsigned b1) {
    asm volatile("mma.sync.aligned.m16n8k16.row.col.f32.f16.f16.f32 "
                 "{%0,%1,%2,%3}, {%4,%5,%6,%7}, {%8,%9}, {%0,%1,%2,%3};"
                 : "+f"(c[0]), "+f"(c[1]), "+f"(c[2]), "+f"(c[3])
                 : "r"(a[0]), "r"(a[1]), "r"(a[2]), "r"(a[3]),
                   "r"(b0), "r"(b1));
}
// fp16-accumulator fp16 MMA (attention S-phase; |s|<=~1.3)
__device__ __forceinline__ void mma_f16h(unsigned c[2], const unsigned a[4],
                                         unsigned b0, unsigned b1) {
    asm volatile("mma.sync.aligned.m16n8k16.row.col.f16.f16.f16.f16 "
                 "{%0,%1}, {%2,%3,%4,%5}, {%6,%7}, {%0,%1};"
                 : "+r"(c[0]), "+r"(c[1])
                 : "r"(a[0]), "r"(a[1]), "r"(a[2]), "r"(a[3]),
                   "r"(b0), "r"(b1));
}
__device__ __forceinline__ void cp16(uint32_t s, const void* g) {
    asm volatile("cp.async.ca.shared.global [%0], [%1], 16;" :: "r"(s), "l"(g));
}

// ---------------------------------------------------------------------------
// Kernel 0: one-shot conversion (x, w -> fp16; bias -> bias*log2e fp16)
// ---------------------------------------------------------------------------
#define NX (BATCH*SEQ*DIM)
#define NW (3*DIM*DIM)
#define NB (SEQ*SEQ)
#define CVT_BLOCKS ((NX+NW+NB)/4/256)

__global__ __launch_bounds__(256) void cvt_inputs(const float* __restrict__ x,
                                                  const float* __restrict__ w,
                                                  const float* __restrict__ bias) {
    size_t i = ((size_t)blockIdx.x * 256 + threadIdx.x) * 4;
    if (i < NX) {
        float4 v = *(const float4*)(x + i);
        *(__half2*)(g_x16 + i)     = __floats2half2_rn(v.x, v.y);
        *(__half2*)(g_x16 + i + 2) = __floats2half2_rn(v.z, v.w);
    } else if (i < NX + NW) {
        size_t j = i - NX;
        float4 v = *(const float4*)(w + j);
        *(__half2*)(g_w16 + j)     = __floats2half2_rn(v.x, v.y);
        *(__half2*)(g_w16 + j + 2) = __floats2half2_rn(v.z, v.w);
    } else {
        size_t j = i - NX - NW;
        float4 v = *(const float4*)(bias + j);
        *(__half2*)(g_bh + j)     = __floats2half2_rn(v.x * LOG2E, v.y * LOG2E);
        *(__half2*)(g_bh + j + 2) = __floats2half2_rn(v.z * LOG2E, v.w * LOG2E);
    }
}

// ---------------------------------------------------------------------------
// Kernel 1: qkv = x @ w^T + b  (fp16 m16n8k16 fp32-accum, cp.async 2-buffer)
// ---------------------------------------------------------------------------
#define LDH   72
#define HTILE (128 * LDH)
#define QKV_SMEM (4 * HTILE * 2)           // 73728 B

__global__ __launch_bounds__(256) void qkv_gemm(const float* __restrict__ bq) {
    extern __shared__ __half qsm[];
    const uint32_t smb = s2u(qsm);

    const int tid  = threadIdx.x;
    const int warp = tid >> 5;
    const int lane = tid & 31;
    const int r0   = lane >> 2;
    const int qq   = lane & 3;
    const int g    = lane >> 3;
    const int lr   = lane & 7;
    const int m_w  = (warp >> 1) * 32;
    const int n_w  = (warp & 1) * 64;

    float C[2][8][4];
#pragma unroll
    for (int i = 0; i < 2; i++)
#pragma unroll
        for (int j = 0; j < 8; j++)
#pragma unroll
            for (int k = 0; k < 4; k++) C[i][j][k] = 0.f;

    const __half* Ag = g_x16 + (size_t)(blockIdx.y * 128) * DIM;
    const __half* Bg = g_w16 + (size_t)(blockIdx.x * 128) * DIM;

    const int cr = tid >> 3;
    const int cc = (tid & 7) * 8;

    const uint32_t aoff = (uint32_t)((m_w + (g & 1) * 8 + lr) * 144 + (g >> 1) * 16);
    const uint32_t boff = (uint32_t)((n_w + (g & 1) * 8 + lr) * 144 + (g >> 1) * 16);

#define QKV_ISSUE(IT, BUF) do {                                                   \
    uint32_t ab = smb + (BUF) * (uint32_t)(HTILE * 2);                            \
    uint32_t bb_ = smb + (uint32_t)(2 * HTILE * 2) + (BUF) * (uint32_t)(HTILE * 2); \
    _Pragma("unroll")                                                             \
    for (int ii_ = 0; ii_ < 4; ii_++) {                                           \
        int r = cr + ii_ * 32;                                                    \
        cp16(ab  + (uint32_t)(r * 144 + cc * 2), Ag + (size_t)r * DIM + (IT) * 64 + cc); \
        cp16(bb_ + (uint32_t)(r * 144 + cc * 2), Bg + (size_t)r * DIM + (IT) * 64 + cc); \
    } } while (0)

    QKV_ISSUE(0, 0);
    asm volatile("cp.async.commit_group;");
    QKV_ISSUE(1, 1);
    asm volatile("cp.async.commit_group;");

    for (int it = 0; it < 12; it++) {
        if (it < 11) asm volatile("cp.async.wait_group 1;");
        else         asm volatile("cp.async.wait_group 0;");
        __syncthreads();

        const uint32_t Ab = smb + (it & 1) * (uint32_t)(HTILE * 2) + aoff;
        const uint32_t Bb = smb + (uint32_t)(2 * HTILE * 2) + (it & 1) * (uint32_t)(HTILE * 2) + boff;
#pragma unroll
        for (int ks = 0; ks < 4; ks++) {
            unsigned a[2][4];
#pragma unroll
            for (int mt = 0; mt < 2; mt++)
                ldsm4(a[mt], Ab + mt * (uint32_t)(16 * 144) + ks * 32);
#pragma unroll
            for (int np = 0; np < 4; np++) {
                unsigned bf[4];
                ldsm4(bf, Bb + np * (uint32_t)(16 * 144) + ks * 32);
#pragma unroll
                for (int mt = 0; mt < 2; mt++) {
                    mma_f16(C[mt][2 * np],     a[mt], bf[0], bf[2]);
                    mma_f16(C[mt][2 * np + 1], a[mt], bf[1], bf[3]);
                }
            }
        }
        __syncthreads();
        if (it + 2 < 12) {
            QKV_ISSUE(it + 2, it & 1);
            asm volatile("cp.async.commit_group;");
        }
    }

    // epilogue: bias add, (q: fold softmax scale), fp16 round, scatter
#pragma unroll
    for (int nt = 0; nt < 8; nt++) {
        int nb = blockIdx.x * 128 + n_w + nt * 8 + 2 * qq;
        float2 bb = *(const float2*)(bq + nb);
        int which = nb / DIM;
        int hn    = nb % DIM;
        int h     = hn >> 6;
        int c0    = hn & 63;
        float sc  = (which == 0) ? QSCALE : 1.0f;
#pragma unroll
        for (int mt = 0; mt < 2; mt++) {
#pragma unroll
            for (int half = 0; half < 2; half++) {
                int m = blockIdx.y * 128 + m_w + mt * 16 + r0 + half * 8;
                int b = m >> 10, s = m & 1023;
                __half2 hv = __floats2half2_rn((C[mt][nt][2 * half + 0] + bb.x) * sc,
                                               (C[mt][nt][2 * half + 1] + bb.y) * sc);
                size_t bh = (size_t)(b * HEADS + h);
                if (which == 0) {
                    *(__half2*)(g_q + (bh * SEQ + s) * DH + c0) = hv;
                } else if (which == 1) {
                    *(__half2*)(g_k + (bh * SEQ + s) * DH + c0) = hv;
                } else {
                    size_t vb = bh * DH * SEQ;
                    g_v[vb + (size_t)c0 * SEQ + s]       = __low2half(hv);
                    g_v[vb + (size_t)(c0 + 1) * SEQ + s] = __high2half(hv);
                }
            }
        }
    }
#undef QKV_ISSUE
}

// ---------------------------------------------------------------------------
// Kernel 2: flash attention, fixed-max softmax, BN=128 keys/iter (8 iters).
// S-phase fp16-accum; P = ex2.approx.f16x2(S + fp16 bias) directly packed.
// l computed on the FMA/ALU pipes (cvt+FADD of P pairs) — NOT the tensor pipe.
// K tile 128x64 (stride 144B), V tile 64x128 transposed (stride 272B),
// triple-buffered cp.async. 256 thr / 8 warps, BM=128, 2 CTAs/SM.
// ---------------------------------------------------------------------------
#define KBYTES (128 * 144)                 // 18432
#define VBYTES (64 * 272)                  // 17408
#define STG    (KBYTES + VBYTES)           // 35840
#define AT_SMEM (3 * STG)                  // 107520

__global__ __launch_bounds__(256, 2) void attn_kernel(const float* __restrict__ dsc,
                                                      float* __restrict__ out) {
    extern __shared__ __half smh[];
    const uint32_t smb = s2u(smh);

    const int tid  = threadIdx.x;
    const int warp = tid >> 5;
    const int lane = tid & 31;
    const int r0   = lane >> 2;
    const int q    = lane & 3;
    const int g    = lane >> 3;
    const int lr   = lane & 7;
    const int wm   = warp * 16;

    const int bh = blockIdx.y;
    const int q0 = blockIdx.x * 128;
    const int b  = bh / HEADS;
    const int h  = bh % HEADS;

    const __half* qg = g_q + ((size_t)bh * SEQ + q0) * DH;
    const __half* kg = g_k + (size_t)bh * SEQ * DH;
    const __half* vg = g_v + (size_t)bh * DH * SEQ;

    // ---- stage Q tile (128x64 fp16, stride 72h) in buffer 0, frags to regs ----
#pragma unroll
    for (int i = 0; i < 4; i++) {
        int id = tid + i * 256;
        int r  = id >> 3;
        int c  = (id & 7) * 8;
        *(uint4*)&smh[r * LDH + c] = *(const uint4*)(qg + (size_t)r * DH + c);
    }
    __syncthreads();

    unsigned Qf[4][4];
    {
        uint32_t qA = smb + (uint32_t)((wm + (g & 1) * 8 + lr) * 144 + (g >> 1) * 16);
#pragma unroll
        for (int ks = 0; ks < 4; ks++)
            ldsm4(Qf[ks], qA + ks * 32);
    }
    __syncthreads();

    // cp.async mappings
    const int kr  = tid >> 3;          // K row 0..31 (+32 per round)
    const int kch = (tid & 7) * 8;     // K col (halves)
    const int vr  = tid >> 4;          // V row 0..15 (+16 per round)
    const int vch = (tid & 15) * 8;    // V col (halves)

#define AT_ISSUE(T, J) do {                                                       \
    uint32_t kb = smb + (uint32_t)((J) * STG);                                    \
    uint32_t vb = kb + (uint32_t)KBYTES;                                          \
    _Pragma("unroll")                                                             \
    for (int ii_ = 0; ii_ < 4; ii_++) {                                           \
        int rk = kr + ii_ * 32;                                                   \
        cp16(kb + (uint32_t)(rk * 144 + kch * 2), kg + (size_t)((T) * 128 + rk) * DH + kch); \
        int rv = vr + ii_ * 16;                                                   \
        cp16(vb + (uint32_t)(rv * 272 + vch * 2), vg + (size_t)rv * SEQ + (T) * 128 + vch); \
    } } while (0)

    AT_ISSUE(0, 0);
    asm volatile("cp.async.commit_group;");
    AT_ISSUE(1, 1);
    asm volatile("cp.async.commit_group;");

    float O[8][4];
#pragma unroll
    for (int nt = 0; nt < 8; nt++)
#pragma unroll
        for (int k = 0; k < 4; k++) O[nt][k] = 0.f;
    float l_lo = 0.f, l_hi = 0.f;      // per-lane partials (FMA pipe)

    const uint32_t fragK = (uint32_t)(((g & 1) * 8 + lr) * 144 + (g >> 1) * 16);
    const uint32_t fragV = (uint32_t)(((g & 1) * 8 + lr) * 272 + (g >> 1) * 16);

    for (int t = 0; t < 8; t++) {
        if (t < 7) asm volatile("cp.async.wait_group 1;");
        else       asm volatile("cp.async.wait_group 0;");
        __syncthreads();
        if (t + 2 < 8) {
            AT_ISSUE(t + 2, (t + 2) % 3);
            asm volatile("cp.async.commit_group;");
        }
        const int j = t % 3;
        const uint32_t kB = smb + (uint32_t)(j * STG) + fragK;
        const uint32_t vB = smb + (uint32_t)(j * STG) + (uint32_t)KBYTES + fragV;

        // ---- bias chunk0 prefetch (fp16, keys 0..63 of this tile) ----
        const __half* bh_lo = g_bh + (size_t)(q0 + wm + r0) * SEQ + t * 128;
        const __half* bh_hi = bh_lo + 8 * SEQ;
        unsigned Bh0[8], Bh1[8];
#pragma unroll
        for (int nt = 0; nt < 8; nt++) {
            Bh0[nt] = *(const unsigned*)(bh_lo + nt * 8 + 2 * q);
            Bh1[nt] = *(const unsigned*)(bh_hi + nt * 8 + 2 * q);
        }

        // ---- S = Q K^T over 128 keys (fp16 accum) ----
        unsigned S16[16][2];
#pragma unroll
        for (int nt = 0; nt < 16; nt++) { S16[nt][0] = 0u; S16[nt][1] = 0u; }

#pragma unroll
        for (int ks = 0; ks < 4; ks++) {
#pragma unroll
            for (int np = 0; np < 8; np++) {
                unsigned bf[4];
                ldsm4(bf, kB + np * (uint32_t)(16 * 144) + ks * 32);
                mma_f16h(S16[2 * np],     Qf[ks], bf[0], bf[2]);
                mma_f16h(S16[2 * np + 1], Qf[ks], bf[1], bf[3]);
            }
        }

        // ---- P chunk0: P = ex2(S + bias), packed fp16; l += P (FMA pipe) ----
#pragma unroll
        for (int nt = 0; nt < 8; nt++) {
            S16[nt][0] = ex2h2(addh2(S16[nt][0], Bh0[nt]));
            S16[nt][1] = ex2h2(addh2(S16[nt][1], Bh1[nt]));
            float2 p0 = __half22float2(*(__half2*)&S16[nt][0]);
            float2 p1 = __half22float2(*(__half2*)&S16[nt][1]);
            l_lo += p0.x + p0.y;
            l_hi += p1.x + p1.y;
        }

        // ---- bias chunk1 loads (keys 64..127; hidden under first PV half) ----
        unsigned Ch0[8], Ch1[8];
#pragma unroll
        for (int nt = 0; nt < 8; nt++) {
            Ch0[nt] = *(const unsigned*)(bh_lo + 64 + nt * 8 + 2 * q);
            Ch1[nt] = *(const unsigned*)(bh_hi + 64 + nt * 8 + 2 * q);
        }

        // ---- PV first half (keys 0..63) ----
#pragma unroll
        for (int ks = 0; ks < 4; ks++) {
            unsigned aP[4] = {S16[2 * ks][0], S16[2 * ks][1],
                              S16[2 * ks + 1][0], S16[2 * ks + 1][1]};
#pragma unroll
            for (int np = 0; np < 4; np++) {
                unsigned bf[4];
                ldsm4(bf, vB + np * (uint32_t)(16 * 272) + ks * 32);
                mma_f16(O[2 * np],     aP, bf[0], bf[2]);
                mma_f16(O[2 * np + 1], aP, bf[1], bf[3]);
            }
        }

        // ---- P chunk1 + l ----
#pragma unroll
        for (int nt = 0; nt < 8; nt++) {
            S16[8 + nt][0] = ex2h2(addh2(S16[8 + nt][0], Ch0[nt]));
            S16[8 + nt][1] = ex2h2(addh2(S16[8 + nt][1], Ch1[nt]));
            float2 p0 = __half22float2(*(__half2*)&S16[8 + nt][0]);
            float2 p1 = __half22float2(*(__half2*)&S16[8 + nt][1]);
            l_lo += p0.x + p0.y;
            l_hi += p1.x + p1.y;
        }

        // ---- PV second half (keys 64..127) ----
#pragma unroll
        for (int ks = 4; ks < 8; ks++) {
            unsigned aP[4] = {S16[2 * ks][0], S16[2 * ks][1],
                              S16[2 * ks + 1][0], S16[2 * ks + 1][1]};
#pragma unroll
            for (int np = 0; np < 4; np++) {
                unsigned bf[4];
                ldsm4(bf, vB + np * (uint32_t)(16 * 272) + ks * 32);
                mma_f16(O[2 * np],     aP, bf[0], bf[2]);
                mma_f16(O[2 * np + 1], aP, bf[1], bf[3]);
            }
        }
    }

    // ---- epilogue: reduce l across 4 lanes, scale, store ----
    {
        l_lo += __shfl_xor_sync(0xffffffffu, l_lo, 1);
        l_lo += __shfl_xor_sync(0xffffffffu, l_lo, 2);
        l_hi += __shfl_xor_sync(0xffffffffu, l_hi, 1);
        l_hi += __shfl_xor_sync(0xffffffffu, l_hi, 2);

        int row_lo = q0 + wm + r0;
        int row_hi = row_lo + 8;
        float sc_lo = dsc[row_lo] / l_lo;
        float sc_hi = dsc[row_hi] / l_hi;
        float* o_lo = out + ((size_t)b * SEQ + row_lo) * DIM + h * DH;
        float* o_hi = out + ((size_t)b * SEQ + row_hi) * DIM + h * DH;
#pragma unroll
        for (int nt = 0; nt < 8; nt++) {
            int c = nt * 8 + 2 * q;
            *(float2*)(o_lo + c) = make_float2(O[nt][0] * sc_lo, O[nt][1] * sc_lo);
            *(float2*)(o_hi + c) = make_float2(O[nt][2] * sc_hi, O[nt][3] * sc_hi);
        }
    }
#undef AT_ISSUE
}

// ---------------------------------------------------------------------------
extern "C" void kernel_launch(void* const* d_in, const int* in_sizes, int n_in,
                              void* d_out, int out_size) {
    const float* x    = (const float*)d_in[0];
    const float* w    = (const float*)d_in[1];
    const float* bq   = (const float*)d_in[2];
    const float* dsc  = (const float*)d_in[3];
    const float* bias = (const float*)d_in[4];
    float* out = (float*)d_out;

    cudaFuncSetAttribute(qkv_gemm, cudaFuncAttributeMaxDynamicSharedMemorySize, QKV_SMEM);
    cudaFuncSetAttribute(attn_kernel, cudaFuncAttributeMaxDynamicSharedMemorySize, AT_SMEM);

    cvt_inputs<<<CVT_BLOCKS, 256>>>(x, w, bias);
    qkv_gemm<<<dim3(18, 128), 256, QKV_SMEM>>>(bq);
    attn_kernel<<<dim3(8, BHT), 256, AT_SMEM>>>(dsc, out);
}

// round 17
// speedup vs baseline: 1.0420x; 1.0420x over previous
#include <cuda_runtime.h>
#include <cuda_fp16.h>
#include <stdint.h>
#include <math.h>

#define SEQ   1024
#define HEADS 12
#define BATCH 16
#define DH    64
#define DIM   768
#define BHT   (BATCH*HEADS)   // 192
#define LOG2E 1.4426950408889634f
#define QSCALE (0.125f * LOG2E)   // folded into stored q

// fp16 operands + attention scratch
__device__ __half g_x16[(size_t)BATCH*SEQ*DIM];
__device__ __half g_w16[(size_t)3*DIM*DIM];
__device__ float  g_bL2[(size_t)SEQ*SEQ];            // bias * log2e (fp32)
__device__ __half g_q[(size_t)BHT*SEQ*DH];           // pre-scaled by 0.125*log2e
__device__ __half g_k[(size_t)BHT*SEQ*DH];
__device__ __half g_v[(size_t)BHT*DH*SEQ];           // TRANSPOSED: [bh][chan][key]

__device__ __forceinline__ float ex2(float x) {
    float r;
    asm("ex2.approx.f32 %0, %1;" : "=f"(r) : "f"(x));
    return r;
}
__device__ __forceinline__ uint32_t s2u(const void* p) {
    return (uint32_t)__cvta_generic_to_shared(p);
}
__device__ __forceinline__ unsigned h2u(__half2 h) {
    return *(unsigned*)&h;
}
__device__ __forceinline__ void ldsm4(unsigned r[4], uint32_t a) {
    asm volatile("ldmatrix.sync.aligned.m8n8.x4.shared.b16 {%0,%1,%2,%3}, [%4];"
                 : "=r"(r[0]), "=r"(r[1]), "=r"(r[2]), "=r"(r[3]) : "r"(a));
}
__device__ __forceinline__ void mma_f16(float c[4], const unsigned a[4],
                                        unsigned b0, unsigned b1) {
    asm volatile("mma.sync.aligned.m16n8k16.row.col.f32.f16.f16.f32 "
                 "{%0,%1,%2,%3}, {%4,%5,%6,%7}, {%8,%9}, {%0,%1,%2,%3};"
                 : "+f"(c[0]), "+f"(c[1]), "+f"(c[2]), "+f"(c[3])
                 : "r"(a[0]), "r"(a[1]), "r"(a[2]), "r"(a[3]),
                   "r"(b0), "r"(b1));
}
__device__ __forceinline__ void cp16(uint32_t s, const void* g) {
    asm volatile("cp.async.ca.shared.global [%0], [%1], 16;" :: "r"(s), "l"(g));
}

// ---------------------------------------------------------------------------
// Kernel 0: one-shot conversion (x, w -> fp16; bias -> bias*log2e fp32)
// ---------------------------------------------------------------------------
#define NX (BATCH*SEQ*DIM)
#define NW (3*DIM*DIM)
#define NB (SEQ*SEQ)
#define CVT_BLOCKS ((NX+NW+NB)/4/256)

__global__ __launch_bounds__(256) void cvt_inputs(const float* __restrict__ x,
                                                  const float* __restrict__ w,
                                                  const float* __restrict__ bias) {
    size_t i = ((size_t)blockIdx.x * 256 + threadIdx.x) * 4;
    if (i < NX) {
        float4 v = *(const float4*)(x + i);
        *(__half2*)(g_x16 + i)     = __floats2half2_rn(v.x, v.y);
        *(__half2*)(g_x16 + i + 2) = __floats2half2_rn(v.z, v.w);
    } else if (i < NX + NW) {
        size_t j = i - NX;
        float4 v = *(const float4*)(w + j);
        *(__half2*)(g_w16 + j)     = __floats2half2_rn(v.x, v.y);
        *(__half2*)(g_w16 + j + 2) = __floats2half2_rn(v.z, v.w);
    } else {
        size_t j = i - NX - NW;
        float4 v = *(const float4*)(bias + j);
        *(float4*)(g_bL2 + j) = make_float4(v.x * LOG2E, v.y * LOG2E, v.z * LOG2E, v.w * LOG2E);
    }
}

// ---------------------------------------------------------------------------
// Kernel 1: qkv = x @ w^T + b  (fp16 m16n8k16, cp.async double-buffer)
// __launch_bounds__(256, 2): force 2 CTAs/SM residency (was 1 -> tensor 50%).
// ---------------------------------------------------------------------------
#define LDH   72
#define HTILE (128 * LDH)
#define QKV_SMEM (4 * HTILE * 2)           // 73728 B

__global__ __launch_bounds__(256, 2) void qkv_gemm(const float* __restrict__ bq) {
    extern __shared__ __half qsm[];
    const uint32_t smb = s2u(qsm);

    const int tid  = threadIdx.x;
    const int warp = tid >> 5;
    const int lane = tid & 31;
    const int r0   = lane >> 2;
    const int qq   = lane & 3;
    const int g    = lane >> 3;
    const int lr   = lane & 7;
    const int m_w  = (warp >> 1) * 32;
    const int n_w  = (warp & 1) * 64;

    float C[2][8][4];
#pragma unroll
    for (int i = 0; i < 2; i++)
#pragma unroll
        for (int j = 0; j < 8; j++)
#pragma unroll
            for (int k = 0; k < 4; k++) C[i][j][k] = 0.f;

    const __half* Ag = g_x16 + (size_t)(blockIdx.y * 128) * DIM;
    const __half* Bg = g_w16 + (size_t)(blockIdx.x * 128) * DIM;

    const int cr = tid >> 3;
    const int cc = (tid & 7) * 8;

    const uint32_t aoff = (uint32_t)((m_w + (g & 1) * 8 + lr) * 144 + (g >> 1) * 16);
    const uint32_t boff = (uint32_t)((n_w + (g & 1) * 8 + lr) * 144 + (g >> 1) * 16);

#define QKV_ISSUE(IT, BUF) do {                                                   \
    uint32_t ab = smb + (BUF) * (uint32_t)(HTILE * 2);                            \
    uint32_t bb_ = smb + (uint32_t)(2 * HTILE * 2) + (BUF) * (uint32_t)(HTILE * 2); \
    _Pragma("unroll")                                                             \
    for (int ii_ = 0; ii_ < 4; ii_++) {                                           \
        int r = cr + ii_ * 32;                                                    \
        cp16(ab  + (uint32_t)(r * 144 + cc * 2), Ag + (size_t)r * DIM + (IT) * 64 + cc); \
        cp16(bb_ + (uint32_t)(r * 144 + cc * 2), Bg + (size_t)r * DIM + (IT) * 64 + cc); \
    } } while (0)

    QKV_ISSUE(0, 0);
    asm volatile("cp.async.commit_group;");
    QKV_ISSUE(1, 1);
    asm volatile("cp.async.commit_group;");

    for (int it = 0; it < 12; it++) {
        if (it < 11) asm volatile("cp.async.wait_group 1;");
        else         asm volatile("cp.async.wait_group 0;");
        __syncthreads();

        const uint32_t Ab = smb + (it & 1) * (uint32_t)(HTILE * 2) + aoff;
        const uint32_t Bb = smb + (uint32_t)(2 * HTILE * 2) + (it & 1) * (uint32_t)(HTILE * 2) + boff;
#pragma unroll
        for (int ks = 0; ks < 4; ks++) {
            unsigned a[2][4];
#pragma unroll
            for (int mt = 0; mt < 2; mt++)
                ldsm4(a[mt], Ab + mt * (uint32_t)(16 * 144) + ks * 32);
#pragma unroll
            for (int np = 0; np < 4; np++) {
                unsigned bf[4];
                ldsm4(bf, Bb + np * (uint32_t)(16 * 144) + ks * 32);
#pragma unroll
                for (int mt = 0; mt < 2; mt++) {
                    mma_f16(C[mt][2 * np],     a[mt], bf[0], bf[2]);
                    mma_f16(C[mt][2 * np + 1], a[mt], bf[1], bf[3]);
                }
            }
        }
        __syncthreads();
        if (it + 2 < 12) {
            QKV_ISSUE(it + 2, it & 1);
            asm volatile("cp.async.commit_group;");
        }
    }

    // epilogue: bias add, (q: fold softmax scale), fp16 round, scatter
#pragma unroll
    for (int nt = 0; nt < 8; nt++) {
        int nb = blockIdx.x * 128 + n_w + nt * 8 + 2 * qq;
        float2 bb = *(const float2*)(bq + nb);
        int which = nb / DIM;
        int hn    = nb % DIM;
        int h     = hn >> 6;
        int c0    = hn & 63;
        float sc  = (which == 0) ? QSCALE : 1.0f;
#pragma unroll
        for (int mt = 0; mt < 2; mt++) {
#pragma unroll
            for (int half = 0; half < 2; half++) {
                int m = blockIdx.y * 128 + m_w + mt * 16 + r0 + half * 8;
                int b = m >> 10, s = m & 1023;
                __half2 hv = __floats2half2_rn((C[mt][nt][2 * half + 0] + bb.x) * sc,
                                               (C[mt][nt][2 * half + 1] + bb.y) * sc);
                size_t bh = (size_t)(b * HEADS + h);
                if (which == 0) {
                    *(__half2*)(g_q + (bh * SEQ + s) * DH + c0) = hv;
                } else if (which == 1) {
                    *(__half2*)(g_k + (bh * SEQ + s) * DH + c0) = hv;
                } else {
                    size_t vb = bh * DH * SEQ;
                    g_v[vb + (size_t)c0 * SEQ + s]       = __low2half(hv);
                    g_v[vb + (size_t)(c0 + 1) * SEQ + s] = __high2half(hv);
                }
            }
        }
    }
#undef QKV_ISSUE
}

// ---------------------------------------------------------------------------
// Kernel 2: flash attention, fp16 m16n8k16, fixed-max softmax (best R9 form).
// Bias prefetched into regs before QK MMA; l via ones-MMA.
// 256 threads / 8 warps, BM=128 (16 rows/warp), BN=64, 2 CTAs/SM.
// ---------------------------------------------------------------------------
#define TILEH (64 * LDH)
#define AT_SMEM (6 * TILEH * 2)            // 55296 B

__global__ __launch_bounds__(256, 2) void attn_kernel(const float* __restrict__ dsc,
                                                      float* __restrict__ out) {
    extern __shared__ __half smh[];
    const uint32_t smb = s2u(smh);

    const int tid  = threadIdx.x;
    const int warp = tid >> 5;
    const int lane = tid & 31;
    const int r0   = lane >> 2;
    const int q    = lane & 3;
    const int g    = lane >> 3;
    const int lr   = lane & 7;
    const int wm   = warp * 16;

    const int bh = blockIdx.y;
    const int q0 = blockIdx.x * 128;
    const int b  = bh / HEADS;
    const int h  = bh % HEADS;

    const __half* qg = g_q + ((size_t)bh * SEQ + q0) * DH;
    const __half* kg = g_k + (size_t)bh * SEQ * DH;
    const __half* vg = g_v + (size_t)bh * DH * SEQ;

    // ---- stage Q tile (128x64 fp16), pull fragments to regs ----
#pragma unroll
    for (int i = 0; i < 4; i++) {
        int id = tid + i * 256;
        int r  = id >> 3;
        int c  = (id & 7) * 8;
        *(uint4*)&smh[r * LDH + c] = *(const uint4*)(qg + (size_t)r * DH + c);
    }
    __syncthreads();

    unsigned Qf[4][4];
    {
        uint32_t qA = smb + (uint32_t)((wm + (g & 1) * 8 + lr) * 144 + (g >> 1) * 16);
#pragma unroll
        for (int ks = 0; ks < 4; ks++)
            ldsm4(Qf[ks], qA + ks * 32);
    }
    __syncthreads();

    const int cr = tid >> 3;
    const int cc = (tid & 7) * 8;

#define AT_ISSUE(T, J) do {                                                       \
    uint32_t kb = smb + (uint32_t)((2 * (J)) * TILEH * 2);                        \
    uint32_t vb = smb + (uint32_t)((2 * (J) + 1) * TILEH * 2);                    \
    _Pragma("unroll")                                                             \
    for (int ii_ = 0; ii_ < 2; ii_++) {                                           \
        int r = cr + ii_ * 32;                                                    \
        cp16(kb + (uint32_t)(r * 144 + cc * 2), kg + (size_t)((T) * 64 + r) * DH + cc); \
        cp16(vb + (uint32_t)(r * 144 + cc * 2), vg + (size_t)r * SEQ + (T) * 64 + cc);  \
    } } while (0)

    AT_ISSUE(0, 0);
    asm volatile("cp.async.commit_group;");
    AT_ISSUE(1, 1);
    asm volatile("cp.async.commit_group;");

    float O[8][4];
#pragma unroll
    for (int nt = 0; nt < 8; nt++)
#pragma unroll
        for (int k = 0; k < 4; k++) O[nt][k] = 0.f;
    float Ol[4] = {0.f, 0.f, 0.f, 0.f};   // l accumulator (col 0 of ones-MMA)

    const unsigned bl_const = (lane < 4) ? 0x3C003C00u : 0u;
    const uint32_t fragoff = (uint32_t)(((g & 1) * 8 + lr) * 144 + (g >> 1) * 16);

    for (int t = 0; t < 16; t++) {
        if (t < 15) asm volatile("cp.async.wait_group 1;");
        else        asm volatile("cp.async.wait_group 0;");
        __syncthreads();
        if (t + 2 < 16) {
            AT_ISSUE(t + 2, (t + 2) % 3);
            asm volatile("cp.async.commit_group;");
        }
        const int j = t % 3;
        const uint32_t kB = smb + (uint32_t)((2 * j) * TILEH * 2) + fragoff;
        const uint32_t vB = smb + (uint32_t)((2 * j + 1) * TILEH * 2) + fragoff;

        // ---- prefetch bias for this tile (no dependency on S -> hidden) ----
        const float* b_lo = g_bL2 + (size_t)(q0 + wm + r0) * SEQ + t * 64;
        const float* b_hi = b_lo + 8 * SEQ;
        float2 B0[8], B1[8];
#pragma unroll
        for (int nt = 0; nt < 8; nt++) {
            B0[nt] = *(const float2*)(b_lo + nt * 8 + 2 * q);
            B1[nt] = *(const float2*)(b_hi + nt * 8 + 2 * q);
        }

        // ---- S = Q K^T  (per warp: 16 x 64; scale pre-folded into Q) ----
        float S[8][4];
#pragma unroll
        for (int nt = 0; nt < 8; nt++)
#pragma unroll
            for (int k = 0; k < 4; k++) S[nt][k] = 0.f;

#pragma unroll
        for (int ks = 0; ks < 4; ks++) {
#pragma unroll
            for (int np = 0; np < 4; np++) {
                unsigned bf[4];
                ldsm4(bf, kB + np * (uint32_t)(16 * 144) + ks * 32);
                mma_f16(S[2 * np],     Qf[ks], bf[0], bf[2]);
                mma_f16(S[2 * np + 1], Qf[ks], bf[1], bf[3]);
            }
        }

        // ---- P = exp2(S + biasL2) ----
#pragma unroll
        for (int nt = 0; nt < 8; nt++) {
            S[nt][0] = ex2(S[nt][0] + B0[nt].x);
            S[nt][1] = ex2(S[nt][1] + B0[nt].y);
            S[nt][2] = ex2(S[nt][2] + B1[nt].x);
            S[nt][3] = ex2(S[nt][3] + B1[nt].y);
        }

        // ---- O += P @ V ; l += P @ ones (constant B-fragment) ----
#pragma unroll
        for (int ks = 0; ks < 4; ks++) {
            unsigned aP[4];
            aP[0] = h2u(__floats2half2_rn(S[2 * ks][0],     S[2 * ks][1]));
            aP[1] = h2u(__floats2half2_rn(S[2 * ks][2],     S[2 * ks][3]));
            aP[2] = h2u(__floats2half2_rn(S[2 * ks + 1][0], S[2 * ks + 1][1]));
            aP[3] = h2u(__floats2half2_rn(S[2 * ks + 1][2], S[2 * ks + 1][3]));
            mma_f16(Ol, aP, bl_const, bl_const);
#pragma unroll
            for (int np = 0; np < 4; np++) {
                unsigned bf[4];
                ldsm4(bf, vB + np * (uint32_t)(16 * 144) + ks * 32);
                mma_f16(O[2 * np],     aP, bf[0], bf[2]);
                mma_f16(O[2 * np + 1], aP, bf[1], bf[3]);
            }
        }
    }

    // ---- epilogue: broadcast l from q==0 lanes, scale, store ----
    {
        const unsigned src = lane & ~3u;
        float l_lo = __shfl_sync(0xffffffffu, Ol[0], src);
        float l_hi = __shfl_sync(0xffffffffu, Ol[2], src);

        int row_lo = q0 + wm + r0;
        int row_hi = row_lo + 8;
        float sc_lo = dsc[row_lo] / l_lo;
        float sc_hi = dsc[row_hi] / l_hi;
        float* o_lo = out + ((size_t)b * SEQ + row_lo) * DIM + h * DH;
        float* o_hi = out + ((size_t)b * SEQ + row_hi) * DIM + h * DH;
#pragma unroll
        for (int nt = 0; nt < 8; nt++) {
            int c = nt * 8 + 2 * q;
            *(float2*)(o_lo + c) = make_float2(O[nt][0] * sc_lo, O[nt][1] * sc_lo);
            *(float2*)(o_hi + c) = make_float2(O[nt][2] * sc_hi, O[nt][3] * sc_hi);
        }
    }
#undef AT_ISSUE
}

// ---------------------------------------------------------------------------
extern "C" void kernel_launch(void* const* d_in, const int* in_sizes, int n_in,
                              void* d_out, int out_size) {
    const float* x    = (const float*)d_in[0];
    const float* w    = (const float*)d_in[1];
    const float* bq   = (const float*)d_in[2];
    const float* dsc  = (const float*)d_in[3];
    const float* bias = (const float*)d_in[4];
    float* out = (float*)d_out;

    cudaFuncSetAttribute(qkv_gemm, cudaFuncAttributeMaxDynamicSharedMemorySize, QKV_SMEM);
    cudaFuncSetAttribute(attn_kernel, cudaFuncAttributeMaxDynamicSharedMemorySize, AT_SMEM);

    cvt_inputs<<<CVT_BLOCKS, 256>>>(x, w, bias);
    qkv_gemm<<<dim3(18, 128), 256, QKV_SMEM>>>(bq);
    attn_kernel<<<dim3(8, BHT), 256, AT_SMEM>>>(dsc, out);
}